// round 16
// baseline (speedup 1.0000x reference)
#include <cuda_runtime.h>
#include <math.h>

#define N_NODES 500000
#define N_EDGES 3000000
#define FULLMASK 0xFFFFFFFFu

// Scratch buffers (device globals — no allocation allowed)
__device__ float  g_h1[N_NODES * 16];   // layer-1 fp32 accumulator (atomic target)
__device__ float4 g_x4[N_NODES];        // padded x for single-load gathers
__device__ float4 g_q[N_NODES];         // q_i = b2a + h_i@(Wtop-Wbot)
__device__ float4 g_r[N_NODES];         // r_j = h_j@Wbot

// ---------------------------------------------------------------------------
// Kernel 0: pack x -> float4 table, zero g_h1.
// ---------------------------------------------------------------------------
__global__ void init_kernel(const float* __restrict__ x) {
    int i = blockIdx.x * blockDim.x + threadIdx.x;
    int stride = gridDim.x * blockDim.x;
    for (int j = i; j < N_NODES; j += stride)
        g_x4[j] = make_float4(x[3 * j], x[3 * j + 1], x[3 * j + 2], 0.f);
    float4* a = (float4*)g_h1;
    const float4 z = make_float4(0.f, 0.f, 0.f, 0.f);
    for (int j = i; j < N_NODES * 4; j += stride) a[j] = z;
}

// float atomic-max via signed/unsigned bit trick (exact, order-independent)
__device__ __forceinline__ void atomic_max_float(float* addr, float v) {
    if (v >= 0.f) atomicMax((int*)addr, __float_as_int(v));
    else          atomicMin((unsigned int*)addr, __float_as_uint(v));
}

// 256-bit load of 8 consecutive floats (Blackwell LDG.E.256).
__device__ __forceinline__ void ld256(const float* p, float* v) {
#if defined(__CUDA_ARCH__) && (__CUDA_ARCH__ >= 1000)
    asm volatile(
        "ld.global.v8.f32 {%0, %1, %2, %3, %4, %5, %6, %7}, [%8];"
        : "=f"(v[0]), "=f"(v[1]), "=f"(v[2]), "=f"(v[3]),
          "=f"(v[4]), "=f"(v[5]), "=f"(v[6]), "=f"(v[7])
        : "l"(p));
#else
    const float4* p4 = (const float4*)p;
    float4 a = p4[0], b = p4[1];
    v[0] = a.x; v[1] = a.y; v[2] = a.z; v[3] = a.w;
    v[4] = b.x; v[5] = b.y; v[6] = b.z; v[7] = b.w;
#endif
}

// ---- packed dual-lane fp32 FMA (sm_100a FFMA2; ptxas won't emit from C++) ----
#if defined(__CUDA_ARCH__) && (__CUDA_ARCH__ >= 1000)
#define HAVE_F32X2 1
__device__ __forceinline__ unsigned long long pk2(float lo, float hi) {
    unsigned long long r;
    asm("mov.b64 %0, {%1, %2};" : "=l"(r) : "f"(lo), "f"(hi));
    return r;
}
__device__ __forceinline__ void upk2(unsigned long long v, float& lo, float& hi) {
    asm("mov.b64 {%0, %1}, %2;" : "=f"(lo), "=f"(hi) : "l"(v));
}
__device__ __forceinline__ void fma2(unsigned long long& d,
                                     unsigned long long a, unsigned long long b) {
    asm("fma.rn.f32x2 %0, %1, %2, %0;" : "+l"(d) : "l"(a), "l"(b));
}
#else
#define HAVE_F32X2 0
#endif

// ---------------------------------------------------------------------------
// Kernel 1: EdgeConv layer 1.  g_x4 -> scatter-max into g_h1[N,16].
// Pair-cooperative probe (1 wf), FFMA2 GEMMs, filtered atomics.
// ---------------------------------------------------------------------------
__global__ void __launch_bounds__(256) edge1_kernel(
    const int* __restrict__ ei,
    const float* __restrict__ w1a, const float* __restrict__ b1a,
    const float* __restrict__ w1b, const float* __restrict__ b1b) {
    __shared__ float sw1a[96], sb1a[16], sw1b[256], sb1b[16];
    int t = threadIdx.x;
    if (t < 96)  sw1a[t] = w1a[t];
    if (t < 16)  { sb1a[t] = b1a[t]; sb1b[t] = b1b[t]; }
    sw1b[t] = w1b[t];                   // blockDim == 256
    __syncthreads();

    int e = blockIdx.x * 256 + t;
    if (e >= N_EDGES) return;           // exits in whole warps (3M % 32 == 0)
    int lane = t & 31;
    int s = ei[e];
    int d = ei[N_EDGES + e];

    // ---- pair-cooperative probe issue (hoisted; latency hides under GEMMs) --
    int dpair = __shfl_xor_sync(FULLMASK, d, 1);
    int odd = lane & 1;
    int dA = odd ? dpair : d;    // even edge's dst
    int dB = odd ? d : dpair;    // odd edge's dst
    float A[8], B[8];
    ld256(g_h1 + (long long)dA * 16 + odd * 8, A);
    ld256(g_h1 + (long long)dB * 16 + odd * 8, B);

    float4 xi = __ldg(&g_x4[d]);
    float4 xj = __ldg(&g_x4[s]);
    float in6[6] = {xi.x, xi.y, xi.z, xj.x - xi.x, xj.y - xi.y, xj.z - xi.z};

#if HAVE_F32X2
    unsigned long long acc[8];
#pragma unroll
    for (int p = 0; p < 8; p++) acc[p] = pk2(sb1a[2 * p], sb1a[2 * p + 1]);
#pragma unroll
    for (int c = 0; c < 6; c++) {
        unsigned long long zc = pk2(in6[c], in6[c]);
        const float* wr = &sw1a[c * 16];
#pragma unroll
        for (int p = 0; p < 8; p++)
            fma2(acc[p], zc, pk2(wr[2 * p], wr[2 * p + 1]));
    }
    float hid[16];
#pragma unroll
    for (int p = 0; p < 8; p++) {
        float lo, hi; upk2(acc[p], lo, hi);
        hid[2 * p] = fmaxf(lo, 0.f); hid[2 * p + 1] = fmaxf(hi, 0.f);
    }
    unsigned long long acc2[8];
#pragma unroll
    for (int p = 0; p < 8; p++) acc2[p] = pk2(sb1b[2 * p], sb1b[2 * p + 1]);
#pragma unroll
    for (int c = 0; c < 16; c++) {
        unsigned long long zc = pk2(hid[c], hid[c]);
        const float* wr = &sw1b[c * 16];
#pragma unroll
        for (int p = 0; p < 8; p++)
            fma2(acc2[p], zc, pk2(wr[2 * p], wr[2 * p + 1]));
    }
    float outv[16];
#pragma unroll
    for (int p = 0; p < 8; p++) upk2(acc2[p], outv[2 * p], outv[2 * p + 1]);
#else
    float hid[16];
#pragma unroll
    for (int k = 0; k < 16; k++) {
        float a = sb1a[k];
#pragma unroll
        for (int c = 0; c < 6; c++) a = fmaf(in6[c], sw1a[c * 16 + k], a);
        hid[k] = fmaxf(a, 0.f);
    }
    float outv[16];
#pragma unroll
    for (int k = 0; k < 16; k++) {
        float a = sb1b[k];
#pragma unroll
        for (int j = 0; j < 16; j++) a = fmaf(hid[j], sw1b[j * 16 + k], a);
        outv[k] = a;
    }
#endif

    // ---- redistribute probe halves ------------------------------------------
    float curlo[8], curhi[8];
#pragma unroll
    for (int i = 0; i < 8; i++) {
        float xA = __shfl_xor_sync(FULLMASK, A[i], 1);
        float xB = __shfl_xor_sync(FULLMASK, B[i], 1);
        curlo[i] = odd ? xB : A[i];
        curhi[i] = odd ? B[i] : xA;
    }

    float* dstp = g_h1 + (long long)d * 16;
#pragma unroll
    for (int k = 0; k < 8; k++) {
        if (outv[k] > 0.f && outv[k] > curlo[k])
            atomicMax((int*)(dstp + k), __float_as_int(outv[k]));
    }
#pragma unroll
    for (int k = 0; k < 8; k++) {
        if (outv[8 + k] > 0.f && outv[8 + k] > curhi[k])
            atomicMax((int*)(dstp + 8 + k), __float_as_int(outv[8 + k]));
    }
}

// ---------------------------------------------------------------------------
// Kernel 1.5: per-node factoring of layer 2's first GEMM + out <- -inf init.
// ---------------------------------------------------------------------------
__global__ void __launch_bounds__(256) qr_kernel(
    const float* __restrict__ w2a, const float* __restrict__ b2a,
    float4* __restrict__ out4) {
    __shared__ float sw[128], sb[4];
    int t = threadIdx.x;
    if (t < 128) sw[t] = w2a[t];
    if (t < 4)   sb[t] = b2a[t];
    __syncthreads();
    int i = blockIdx.x * 256 + t;
    if (i >= N_NODES) return;

    const float NI = __int_as_float(0xFF800000);
    out4[i] = make_float4(NI, NI, NI, NI);

    float h[16];
    const float4* hp = (const float4*)(g_h1 + (long long)i * 16);
#pragma unroll
    for (int q = 0; q < 4; q++) {
        float4 c = hp[q];
        h[4 * q] = c.x; h[4 * q + 1] = c.y; h[4 * q + 2] = c.z; h[4 * q + 3] = c.w;
    }

    float q[4], r[4];
#pragma unroll
    for (int n = 0; n < 4; n++) {
        float aq = sb[n], ar = 0.f;
#pragma unroll
        for (int c = 0; c < 16; c++) {
            float wb = sw[(16 + c) * 4 + n];
            aq = fmaf(h[c], sw[c * 4 + n] - wb, aq);
            ar = fmaf(h[c], wb, ar);
        }
        q[n] = aq; r[n] = ar;
    }
    g_q[i] = make_float4(q[0], q[1], q[2], q[3]);
    g_r[i] = make_float4(r[0], r[1], r[2], r[3]);
}

// ---------------------------------------------------------------------------
// Kernel 2: EdgeConv layer 2, factored, 2 edges/thread for MLP.
// Per edge: q[d] gather + r[s] gather + out probe (all hoisted, both edges
// issued back-to-back -> 6 independent loads in flight per thread).
// ---------------------------------------------------------------------------
__global__ void __launch_bounds__(256) edge2_kernel(
    const int* __restrict__ ei,
    const float* __restrict__ w2b, const float* __restrict__ b2b,
    float* __restrict__ out) {
    __shared__ float sw[16], sb[4];
    int t = threadIdx.x;
    if (t < 16) sw[t] = w2b[t];
    if (t < 4)  sb[t] = b2b[t];
    __syncthreads();

    int e0 = blockIdx.x * 512 + t;        // first coalesced segment
    int e1 = e0 + 256;                    // second coalesced segment
    bool v0 = e0 < N_EDGES, v1 = e1 < N_EDGES;
    if (!v0) return;

    int s0 = ei[e0], d0 = ei[N_EDGES + e0];
    int s1 = 0, d1 = 0;
    if (v1) { s1 = ei[e1]; d1 = ei[N_EDGES + e1]; }

    // Issue all 6 scattered loads up front (independent chains)
    float* dst0 = out + (long long)d0 * 4;
    float4 c0 = *((const float4*)dst0);
    float4 qv0 = __ldg(&g_q[d0]);
    float4 rv0 = __ldg(&g_r[s0]);
    float* dst1 = dst0;
    float4 c1, qv1, rv1;
    if (v1) {
        dst1 = out + (long long)d1 * 4;
        c1 = *((const float4*)dst1);
        qv1 = __ldg(&g_q[d1]);
        rv1 = __ldg(&g_r[s1]);
    }

    {
        float z[4] = {fmaxf(qv0.x + rv0.x, 0.f), fmaxf(qv0.y + rv0.y, 0.f),
                      fmaxf(qv0.z + rv0.z, 0.f), fmaxf(qv0.w + rv0.w, 0.f)};
        float cur[4] = {c0.x, c0.y, c0.z, c0.w};
#pragma unroll
        for (int k = 0; k < 4; k++) {
            float a = sb[k];
#pragma unroll
            for (int j = 0; j < 4; j++) a = fmaf(z[j], sw[j * 4 + k], a);
            if (!(a <= cur[k]))
                atomic_max_float(dst0 + k, a);
        }
    }
    if (v1) {
        float z[4] = {fmaxf(qv1.x + rv1.x, 0.f), fmaxf(qv1.y + rv1.y, 0.f),
                      fmaxf(qv1.z + rv1.z, 0.f), fmaxf(qv1.w + rv1.w, 0.f)};
        float cur[4] = {c1.x, c1.y, c1.z, c1.w};
#pragma unroll
        for (int k = 0; k < 4; k++) {
            float a = sb[k];
#pragma unroll
            for (int j = 0; j < 4; j++) a = fmaf(z[j], sw[j * 4 + k], a);
            if (!(a <= cur[k]))
                atomic_max_float(dst1 + k, a);
        }
    }
}

// ---------------------------------------------------------------------------
// Kernel 3: finalize.  -inf -> 0, then log_softmax over the 4 channels.
// ---------------------------------------------------------------------------
__global__ void __launch_bounds__(256) finalize_kernel(float4* __restrict__ out4) {
    int i = blockIdx.x * 256 + threadIdx.x;
    if (i >= N_NODES) return;
    float4 v = out4[i];
    if (!isfinite(v.x)) v.x = 0.f;
    if (!isfinite(v.y)) v.y = 0.f;
    if (!isfinite(v.z)) v.z = 0.f;
    if (!isfinite(v.w)) v.w = 0.f;
    float m = fmaxf(fmaxf(v.x, v.y), fmaxf(v.z, v.w));
    float s = expf(v.x - m) + expf(v.y - m) + expf(v.z - m) + expf(v.w - m);
    float l = m + logf(s);
    v.x -= l; v.y -= l; v.z -= l; v.w -= l;
    out4[i] = v;
}

extern "C" void kernel_launch(void* const* d_in, const int* in_sizes, int n_in,
                              void* d_out, int out_size) {
    const float* x   = (const float*)d_in[0];
    const int*   ei  = (const int*)d_in[1];
    const float* w1a = (const float*)d_in[2];
    const float* b1a = (const float*)d_in[3];
    const float* w1b = (const float*)d_in[4];
    const float* b1b = (const float*)d_in[5];
    const float* w2a = (const float*)d_in[6];
    const float* b2a = (const float*)d_in[7];
    const float* w2b = (const float*)d_in[8];
    const float* b2b = (const float*)d_in[9];
    float* out = (float*)d_out;

    init_kernel<<<2048, 256>>>(x);
    int eb  = (N_EDGES + 255) / 256;
    int eb2 = (N_EDGES + 511) / 512;
    int nb  = (N_NODES + 255) / 256;
    edge1_kernel<<<eb, 256>>>(ei, w1a, b1a, w1b, b1b);
    qr_kernel<<<nb, 256>>>(w2a, b2a, (float4*)out);
    edge2_kernel<<<eb2, 256>>>(ei, w2b, b2b, out);
    finalize_kernel<<<nb, 256>>>((float4*)out);
}